// round 10
// baseline (speedup 1.0000x reference)
#include <cuda_runtime.h>
#include <cstdint>

#define NSUB 8
#define BTOK 4096
#define DIN  512
#define DFF  2048
#define DOUT 512
#define MAXT   40        // BM=128 tiles: sum ceil(cnt/128) <= 32+7 = 39
#define MAXT64 72        // BM=64  tiles: sum ceil(cnt/64)  <= 64+7 = 71

// ---- device-global scratch ----
__device__ int   g_tok[BTOK];
__device__ int   g_off[NSUB + 1];
__device__ int   g_te128[MAXT],   g_tm128[MAXT];
__device__ int   g_te64[MAXT64],  g_tm64[MAXT64];
__device__ float g_x[(size_t)BTOK * DIN];   // compact, tf32-rounded x
__device__ float g_h[(size_t)BTOK * DFF];   // intermediate h (tf32-rounded)

// ===========================================================================
// Routing + tile tables (both BM=128 and BM=64 granularity)
// ===========================================================================
__global__ void route_kernel(const int* __restrict__ groups)
{
    __shared__ int s_cnt[NSUB];
    __shared__ int s_cur[NSUB];
    const int tid = threadIdx.x;
    if (tid < NSUB) s_cnt[tid] = 0;
    __syncthreads();
    for (int b = tid; b < BTOK; b += blockDim.x)
        atomicAdd(&s_cnt[groups[2 * b]], 1);
    __syncthreads();
    if (tid == 0) {
        int off = 0, t1 = 0, t2 = 0;
        for (int e = 0; e < NSUB; ++e) {
            g_off[e] = off; s_cur[e] = off;
            for (int m0 = 0; m0 < s_cnt[e]; m0 += 128) {
                g_te128[t1] = e; g_tm128[t1] = m0; ++t1;
            }
            for (int m0 = 0; m0 < s_cnt[e]; m0 += 64) {
                g_te64[t2] = e; g_tm64[t2] = m0; ++t2;
            }
            off += s_cnt[e];
        }
        g_off[NSUB] = off;
        for (; t1 < MAXT;   ++t1) { g_te128[t1] = -1; g_tm128[t1] = 0; }
        for (; t2 < MAXT64; ++t2) { g_te64[t2]  = -1; g_tm64[t2]  = 0; }
    }
    __syncthreads();
    for (int b = tid; b < BTOK; b += blockDim.x) {
        int e = groups[2 * b];
        int pos = atomicAdd(&s_cur[e], 1);
        g_tok[pos] = b;
    }
}

// ===========================================================================
// helpers
// ===========================================================================
__device__ __forceinline__ uint32_t f2tf(float x) {
    uint32_t u;
    asm("cvt.rna.tf32.f32 %0, %1;" : "=r"(u) : "f"(x));
    return u;
}
__device__ __forceinline__ void mma8(float* c, const uint32_t* a, const uint32_t* b) {
    asm volatile(
        "mma.sync.aligned.m16n8k8.row.col.f32.tf32.tf32.f32 "
        "{%0,%1,%2,%3}, {%4,%5,%6,%7}, {%8,%9}, {%0,%1,%2,%3};"
        : "+f"(c[0]), "+f"(c[1]), "+f"(c[2]), "+f"(c[3])
        : "r"(a[0]), "r"(a[1]), "r"(a[2]), "r"(a[3]), "r"(b[0]), "r"(b[1]));
}
__device__ __forceinline__ void cp16(uint32_t dst_smem, const void* src) {
    asm volatile("cp.async.cg.shared.global [%0], [%1], 16;"
                 :: "r"(dst_smem), "l"(src));
}
__device__ __forceinline__ uint32_t smem_u32(const void* p) {
    uint32_t a;
    asm("{ .reg .u64 t; cvta.to.shared.u64 t, %1; cvt.u32.u64 %0, t; }" : "=r"(a) : "l"(p));
    return a;
}

// ===========================================================================
// Gather + tf32-round x into compact token order.
// ===========================================================================
__global__ void gather_x(const float* __restrict__ x)
{
    const int r   = blockIdx.x;
    const int tok = g_tok[r];
    float4 v = *(((const float4*)(x + (size_t)tok * DIN)) + threadIdx.x);
    v.x = __uint_as_float(f2tf(v.x));
    v.y = __uint_as_float(f2tf(v.y));
    v.z = __uint_as_float(f2tf(v.z));
    v.w = __uint_as_float(f2tf(v.w));
    *(((float4*)(g_x + (size_t)r * DIN)) + threadIdx.x) = v;
}

// ===========================================================================
// tf32 mma.sync GEMM, BM x 128 tile (BM in {128, 64}), BK=16, 3-stage
// cp.async pipeline, tile-table scheduling. A pre-rounded; B cvt at read.
//   FIRST:  h = relu(g_x @ W1[e] + b1)  -> g_h (tf32-rounded, compact rows)
//   !FIRST: y = g_h @ W2[e] + b2        -> out (scatter by token)
// Warp layout: warps_m = BM/32, warps_n = 8/warps_m; warp tile 32 x (128/warps_n).
// ===========================================================================
template <int K, int NTOT, bool FIRST, int BM>
__global__ __launch_bounds__(256)
void moe_mma_gemm(const float* __restrict__ W,
                  const float* __restrict__ bias,
                  float* __restrict__ Y)
{
    constexpr int KT     = K / 16;
    constexpr int ABYTES = BM * 64;            // A stage bytes
    constexpr int STAGE  = ABYTES + 8192;      // + B stage (16k x 128 f)
    constexpr int NF     = BM / 16;            // n8 frags per warp (8 or 4)
    constexpr int AJ     = BM / 64;            // A cp.async segs per thread
    constexpr int WMM    = BM / 32 - 1;        // wm mask (3 or 1)
    constexpr int WNS    = (BM == 128) ? 2 : 1;// wn shift

    const int* te = (BM == 128) ? g_te128 : g_te64;
    const int* tm = (BM == 128) ? g_tm128 : g_tm64;

    const int e = te[blockIdx.y];
    if (e < 0) return;
    const int m0  = tm[blockIdx.y];
    const int off = g_off[e];
    const int cnt = g_off[e + 1] - off;
    const int n0  = blockIdx.x * 128;

    const float* A = FIRST ? g_x : g_h;

    extern __shared__ char sm[];
    const uint32_t smu = smem_u32(sm);

    const int tid = threadIdx.x;
    const int wid = tid >> 5, l = tid & 31;
    const int g = l >> 2, tig = l & 3;
    const int wm = wid & WMM;
    const int wn = wid >> WNS;

    // ---- cp.async mappings ----
    const char* aCpPtr[AJ];
    uint32_t    aCpOff[AJ];
    #pragma unroll
    for (int j = 0; j < AJ; ++j) {
        const int row = (tid >> 2) + 64 * j;
        const int c4  = tid & 3;
        const int r   = m0 + row;
        const int rr  = (r < cnt) ? r : (cnt - 1);
        aCpPtr[j] = (const char*)(A + (size_t)(off + rr) * K) + c4 * 16;
        aCpOff[j] = row * 64 + ((c4 ^ ((row >> 1) & 3)) << 4);
    }
    const char* bCpPtr[2];
    uint32_t    bCpOff[2];
    #pragma unroll
    for (int j = 0; j < 2; ++j) {
        const int lr = (tid >> 5) + 8 * j;
        const int n4 = tid & 31;
        bCpPtr[j] = (const char*)(W + (size_t)e * K * NTOT + (size_t)lr * NTOT + n0 + n4 * 4);
        bCpOff[j] = ABYTES + lr * 512 + ((n4 ^ ((lr & 3) << 1)) << 4);
    }

    // ---- fragment-read bases ----
    uint32_t rowb[4], uxr[4];
    #pragma unroll
    for (int mf = 0; mf < 2; ++mf)
        #pragma unroll
        for (int h = 0; h < 2; ++h) {
            const int R = wm * 32 + mf * 16 + g + 8 * h;
            rowb[mf * 2 + h] = R * 64 + tig * 4;
            uxr [mf * 2 + h] = (R >> 1) & 3;
        }
    uint32_t bRd[NF];
    #pragma unroll
    for (int nf = 0; nf < NF; ++nf) {
        const int n4f = wn * (NF * 2) + nf * 2 + (g >> 2);
        bRd[nf] = ABYTES + ((n4f ^ (tig << 1)) << 4) + (g & 3) * 4 + tig * 512;
    }

    float acc[2][NF][4];
    #pragma unroll
    for (int i = 0; i < 2; ++i)
        #pragma unroll
        for (int j = 0; j < NF; ++j)
            #pragma unroll
            for (int r = 0; r < 4; ++r) acc[i][j][r] = 0.0f;

    auto issue = [&](int kt, int s) {
        const uint32_t sb = smu + s * STAGE;
        const size_t astep = (size_t)kt * 64;
        const size_t bstep = (size_t)kt * 16 * NTOT * 4;
        #pragma unroll
        for (int j = 0; j < AJ; ++j) cp16(sb + aCpOff[j], aCpPtr[j] + astep);
        #pragma unroll
        for (int j = 0; j < 2; ++j) cp16(sb + bCpOff[j], bCpPtr[j] + bstep);
    };

    issue(0, 0);
    asm volatile("cp.async.commit_group;" ::: "memory");
    issue(1, 1);
    asm volatile("cp.async.commit_group;" ::: "memory");

    #pragma unroll 1
    for (int kt = 0; kt < KT; ++kt) {
        asm volatile("cp.async.wait_group 1;" ::: "memory");
        __syncthreads();
        if (kt + 2 < KT) issue(kt + 2, (kt + 2) % 3);
        asm volatile("cp.async.commit_group;" ::: "memory");

        const char* base = sm + (kt % 3) * STAGE;
        #pragma unroll
        for (int ks = 0; ks < 2; ++ks) {
            uint32_t A0[2][4];
            #pragma unroll
            for (int mf = 0; mf < 2; ++mf) {
                const char* rb0 = base + rowb[mf * 2];
                const char* rb1 = base + rowb[mf * 2 + 1];
                A0[mf][0] = *(const uint32_t*)(rb0 + (((2u * ks)     ^ uxr[mf * 2])     << 4));
                A0[mf][1] = *(const uint32_t*)(rb1 + (((2u * ks)     ^ uxr[mf * 2 + 1]) << 4));
                A0[mf][2] = *(const uint32_t*)(rb0 + (((2u * ks + 1) ^ uxr[mf * 2])     << 4));
                A0[mf][3] = *(const uint32_t*)(rb1 + (((2u * ks + 1) ^ uxr[mf * 2 + 1]) << 4));
            }
            #pragma unroll
            for (int nf = 0; nf < NF; ++nf) {
                const float fb0 = *(const float*)(base + bRd[nf] + ks * 4096u);
                const float fb1 = *(const float*)(base + bRd[nf] + ks * 4096u + 2048u);
                uint32_t B0[2] = { f2tf(fb0), f2tf(fb1) };
                mma8(acc[0][nf], A0[0], B0);
                mma8(acc[1][nf], A0[1], B0);
            }
        }
    }
    __syncthreads();

    // ---- epilogue: passes of 64 rows through smem staging [64][132] ----
    float* stg = (float*)sm;
    #pragma unroll 1
    for (int pass = 0; pass < BM / 64; ++pass) {
        if ((wm >> 1) == pass) {
            #pragma unroll
            for (int mf = 0; mf < 2; ++mf)
                #pragma unroll
                for (int nf = 0; nf < NF; ++nf) {
                    const int rl  = (wm & 1) * 32 + mf * 16 + g;
                    const int col = wn * (NF * 8) + nf * 8 + 2 * tig;
                    *(float2*)&stg[rl * 132 + col] =
                        make_float2(acc[mf][nf][0], acc[mf][nf][1]);
                    *(float2*)&stg[(rl + 8) * 132 + col] =
                        make_float2(acc[mf][nf][2], acc[mf][nf][3]);
                }
        }
        __syncthreads();
        {
            const int rl = tid >> 2;
            const int q  = tid & 3;
            const int rm = m0 + pass * 64 + rl;
            if (rm < cnt) {
                float* dst;
                if (FIRST) dst = g_h + (size_t)(off + rm) * DFF + n0 + q * 32;
                else       dst = Y   + (size_t)g_tok[off + rm] * DOUT + n0 + q * 32;
                const float* bsrc = bias + (size_t)e * NTOT + n0 + q * 32;
                const float* s    = stg + rl * 132 + q * 32;
                #pragma unroll
                for (int j = 0; j < 8; ++j) {
                    float4 v  = *(const float4*)(s + 4 * j);
                    float4 bb = *(const float4*)(bsrc + 4 * j);
                    v.x += bb.x; v.y += bb.y; v.z += bb.z; v.w += bb.w;
                    if (FIRST) {
                        v.x = __uint_as_float(f2tf(fmaxf(v.x, 0.f)));
                        v.y = __uint_as_float(f2tf(fmaxf(v.y, 0.f)));
                        v.z = __uint_as_float(f2tf(fmaxf(v.z, 0.f)));
                        v.w = __uint_as_float(f2tf(fmaxf(v.w, 0.f)));
                    }
                    *(float4*)(dst + 4 * j) = v;
                }
            }
        }
        __syncthreads();
    }
}

// ===========================================================================
// kernel_launch: route -> gather_x -> GEMM1(128x128) -> GEMM2(64x128).
// No allocs, no syncs, no cudaFuncSetAttribute (smem <= 48KB).
// ===========================================================================
extern "C" void kernel_launch(void* const* d_in, const int* in_sizes, int n_in,
                              void* d_out, int out_size)
{
    const float* x      = (const float*)d_in[0];
    const int*   groups = (const int*)  d_in[1];
    const float* W1     = (const float*)d_in[2];
    const float* b1     = (const float*)d_in[3];
    const float* W2     = (const float*)d_in[4];
    const float* b2     = (const float*)d_in[5];
    float*       out    = (float*)d_out;

    constexpr int SMEM1 = 3 * (128 * 64 + 8192);   // 49152 (48KB cap exactly)
    constexpr int SMEM2 = 3 * (64 * 64 + 8192);    // 36864

    route_kernel<<<1, 512>>>(groups);
    gather_x<<<BTOK, DIN / 4>>>(x);
    moe_mma_gemm<DIN, DFF, true,  128><<<dim3(DFF / 128, MAXT),   256, SMEM1>>>(W1, b1, nullptr);
    moe_mma_gemm<DFF, DOUT, false, 64><<<dim3(DOUT / 128, MAXT64), 256, SMEM2>>>(W2, b2, out);
}

// round 11
// speedup vs baseline: 1.0207x; 1.0207x over previous
#include <cuda_runtime.h>
#include <cstdint>

#define NSUB 8
#define BTOK 4096
#define DIN  512
#define DFF  2048
#define DOUT 512
#define MAXT   40        // BM=128 tiles: sum ceil(cnt/128) <= 32+7 = 39
#define MAXT64 72        // BM=64  tiles: sum ceil(cnt/64)  <= 64+7 = 71

// ---- device-global scratch ----
__device__ int   g_tok[BTOK];
__device__ int   g_off[NSUB + 1];
__device__ int   g_te128[MAXT],   g_tm128[MAXT];
__device__ int   g_te64[MAXT64],  g_tm64[MAXT64];
__device__ float g_x[(size_t)BTOK * DIN];   // compact, tf32-rounded x
__device__ float g_h[(size_t)BTOK * DFF];   // intermediate h (tf32-rounded)

// ===========================================================================
// Routing + tile tables (both BM=128 and BM=64 granularity)
// ===========================================================================
__global__ void route_kernel(const int* __restrict__ groups)
{
    __shared__ int s_cnt[NSUB];
    __shared__ int s_cur[NSUB];
    const int tid = threadIdx.x;
    if (tid < NSUB) s_cnt[tid] = 0;
    __syncthreads();
    for (int b = tid; b < BTOK; b += blockDim.x)
        atomicAdd(&s_cnt[groups[2 * b]], 1);
    __syncthreads();
    if (tid == 0) {
        int off = 0, t1 = 0, t2 = 0;
        for (int e = 0; e < NSUB; ++e) {
            g_off[e] = off; s_cur[e] = off;
            for (int m0 = 0; m0 < s_cnt[e]; m0 += 128) {
                g_te128[t1] = e; g_tm128[t1] = m0; ++t1;
            }
            for (int m0 = 0; m0 < s_cnt[e]; m0 += 64) {
                g_te64[t2] = e; g_tm64[t2] = m0; ++t2;
            }
            off += s_cnt[e];
        }
        g_off[NSUB] = off;
        for (; t1 < MAXT;   ++t1) { g_te128[t1] = -1; g_tm128[t1] = 0; }
        for (; t2 < MAXT64; ++t2) { g_te64[t2]  = -1; g_tm64[t2]  = 0; }
    }
    __syncthreads();
    for (int b = tid; b < BTOK; b += blockDim.x) {
        int e = groups[2 * b];
        int pos = atomicAdd(&s_cur[e], 1);
        g_tok[pos] = b;
    }
}

// ===========================================================================
// helpers
// ===========================================================================
__device__ __forceinline__ uint32_t f2tf(float x) {
    uint32_t u;
    asm("cvt.rna.tf32.f32 %0, %1;" : "=r"(u) : "f"(x));
    return u;
}
// NOTE: non-volatile — pure register computation; lets ptxas software-pipeline
// mma with loads across the unrolled chunk body.
__device__ __forceinline__ void mma8(float* c, const uint32_t* a, const uint32_t* b) {
    asm("mma.sync.aligned.m16n8k8.row.col.f32.tf32.tf32.f32 "
        "{%0,%1,%2,%3}, {%4,%5,%6,%7}, {%8,%9}, {%0,%1,%2,%3};"
        : "+f"(c[0]), "+f"(c[1]), "+f"(c[2]), "+f"(c[3])
        : "r"(a[0]), "r"(a[1]), "r"(a[2]), "r"(a[3]), "r"(b[0]), "r"(b[1]));
}
__device__ __forceinline__ void cp16(uint32_t dst_smem, const void* src) {
    asm volatile("cp.async.cg.shared.global [%0], [%1], 16;"
                 :: "r"(dst_smem), "l"(src));
}
__device__ __forceinline__ uint32_t smem_u32(const void* p) {
    uint32_t a;
    asm("{ .reg .u64 t; cvta.to.shared.u64 t, %1; cvt.u32.u64 %0, t; }" : "=r"(a) : "l"(p));
    return a;
}

// ===========================================================================
// Gather + tf32-round x into compact token order.
// ===========================================================================
__global__ void gather_x(const float* __restrict__ x)
{
    const int r   = blockIdx.x;
    const int tok = g_tok[r];
    float4 v = *(((const float4*)(x + (size_t)tok * DIN)) + threadIdx.x);
    v.x = __uint_as_float(f2tf(v.x));
    v.y = __uint_as_float(f2tf(v.y));
    v.z = __uint_as_float(f2tf(v.z));
    v.w = __uint_as_float(f2tf(v.w));
    *(((float4*)(g_x + (size_t)r * DIN)) + threadIdx.x) = v;
}

// ===========================================================================
// tf32 mma.sync GEMM, BM x 128 tile (BM in {128, 64}), BK=16, 3-stage
// cp.async pipeline, tile-table scheduling. A pre-rounded; B cvt at read.
// Chunk body: hoisted fragment loads -> cvts -> mma burst (scheduler-friendly).
// ===========================================================================
template <int K, int NTOT, bool FIRST, int BM>
__global__ __launch_bounds__(256, 2)
void moe_mma_gemm(const float* __restrict__ W,
                  const float* __restrict__ bias,
                  float* __restrict__ Y)
{
    constexpr int KT     = K / 16;
    constexpr int ABYTES = BM * 64;            // A stage bytes
    constexpr int STAGE  = ABYTES + 8192;      // + B stage (16k x 128 f)
    constexpr int NF     = BM / 16;            // n8 frags per warp (8 or 4)
    constexpr int AJ     = BM / 64;            // A cp.async segs per thread
    constexpr int WMM    = BM / 32 - 1;        // wm mask (3 or 1)
    constexpr int WNS    = (BM == 128) ? 2 : 1;// wn shift
    constexpr int NB     = (NF > 4) ? 4 : NF;  // mma-burst width (reg pressure cap)

    const int* te = (BM == 128) ? g_te128 : g_te64;
    const int* tm = (BM == 128) ? g_tm128 : g_tm64;

    const int e = te[blockIdx.y];
    if (e < 0) return;
    const int m0  = tm[blockIdx.y];
    const int off = g_off[e];
    const int cnt = g_off[e + 1] - off;
    const int n0  = blockIdx.x * 128;

    const float* A = FIRST ? g_x : g_h;

    extern __shared__ char sm[];
    const uint32_t smu = smem_u32(sm);

    const int tid = threadIdx.x;
    const int wid = tid >> 5, l = tid & 31;
    const int g = l >> 2, tig = l & 3;
    const int wm = wid & WMM;
    const int wn = wid >> WNS;

    // ---- cp.async mappings ----
    const char* aCpPtr[AJ];
    uint32_t    aCpOff[AJ];
    #pragma unroll
    for (int j = 0; j < AJ; ++j) {
        const int row = (tid >> 2) + 64 * j;
        const int c4  = tid & 3;
        const int r   = m0 + row;
        const int rr  = (r < cnt) ? r : (cnt - 1);
        aCpPtr[j] = (const char*)(A + (size_t)(off + rr) * K) + c4 * 16;
        aCpOff[j] = row * 64 + ((c4 ^ ((row >> 1) & 3)) << 4);
    }
    const char* bCpPtr[2];
    uint32_t    bCpOff[2];
    #pragma unroll
    for (int j = 0; j < 2; ++j) {
        const int lr = (tid >> 5) + 8 * j;
        const int n4 = tid & 31;
        bCpPtr[j] = (const char*)(W + (size_t)e * K * NTOT + (size_t)lr * NTOT + n0 + n4 * 4);
        bCpOff[j] = ABYTES + lr * 512 + ((n4 ^ ((lr & 3) << 1)) << 4);
    }

    // ---- fragment-read bases ----
    uint32_t rowb[4], uxr[4];
    #pragma unroll
    for (int mf = 0; mf < 2; ++mf)
        #pragma unroll
        for (int h = 0; h < 2; ++h) {
            const int R = wm * 32 + mf * 16 + g + 8 * h;
            rowb[mf * 2 + h] = R * 64 + tig * 4;
            uxr [mf * 2 + h] = (R >> 1) & 3;
        }
    uint32_t bRd[NF];
    #pragma unroll
    for (int nf = 0; nf < NF; ++nf) {
        const int n4f = wn * (NF * 2) + nf * 2 + (g >> 2);
        bRd[nf] = ABYTES + ((n4f ^ (tig << 1)) << 4) + (g & 3) * 4 + tig * 512;
    }

    float acc[2][NF][4];
    #pragma unroll
    for (int i = 0; i < 2; ++i)
        #pragma unroll
        for (int j = 0; j < NF; ++j)
            #pragma unroll
            for (int r = 0; r < 4; ++r) acc[i][j][r] = 0.0f;

    auto issue = [&](int kt, int s) {
        const uint32_t sb = smu + s * STAGE;
        const size_t astep = (size_t)kt * 64;
        const size_t bstep = (size_t)kt * 16 * NTOT * 4;
        #pragma unroll
        for (int j = 0; j < AJ; ++j) cp16(sb + aCpOff[j], aCpPtr[j] + astep);
        #pragma unroll
        for (int j = 0; j < 2; ++j) cp16(sb + bCpOff[j], bCpPtr[j] + bstep);
    };

    issue(0, 0);
    asm volatile("cp.async.commit_group;" ::: "memory");
    issue(1, 1);
    asm volatile("cp.async.commit_group;" ::: "memory");

    #pragma unroll 1
    for (int kt = 0; kt < KT; ++kt) {
        asm volatile("cp.async.wait_group 1;" ::: "memory");
        __syncthreads();
        if (kt + 2 < KT) issue(kt + 2, (kt + 2) % 3);
        asm volatile("cp.async.commit_group;" ::: "memory");

        const char* base = sm + (kt % 3) * STAGE;
        #pragma unroll
        for (int ks = 0; ks < 2; ++ks) {
            uint32_t A0[2][4];
            #pragma unroll
            for (int mf = 0; mf < 2; ++mf) {
                const char* rb0 = base + rowb[mf * 2];
                const char* rb1 = base + rowb[mf * 2 + 1];
                A0[mf][0] = *(const uint32_t*)(rb0 + (((2u * ks)     ^ uxr[mf * 2])     << 4));
                A0[mf][1] = *(const uint32_t*)(rb1 + (((2u * ks)     ^ uxr[mf * 2 + 1]) << 4));
                A0[mf][2] = *(const uint32_t*)(rb0 + (((2u * ks + 1) ^ uxr[mf * 2])     << 4));
                A0[mf][3] = *(const uint32_t*)(rb1 + (((2u * ks + 1) ^ uxr[mf * 2 + 1]) << 4));
            }
            // hoisted B loads -> cvts -> mma burst, NB frags at a time
            #pragma unroll
            for (int nb0 = 0; nb0 < NF; nb0 += NB) {
                uint32_t B0[NB][2];
                #pragma unroll
                for (int q = 0; q < NB; ++q) {
                    const float fb0 = *(const float*)(base + bRd[nb0 + q] + ks * 4096u);
                    const float fb1 = *(const float*)(base + bRd[nb0 + q] + ks * 4096u + 2048u);
                    B0[q][0] = f2tf(fb0);
                    B0[q][1] = f2tf(fb1);
                }
                #pragma unroll
                for (int q = 0; q < NB; ++q) {
                    mma8(acc[0][nb0 + q], A0[0], B0[q]);
                    mma8(acc[1][nb0 + q], A0[1], B0[q]);
                }
            }
        }
    }
    __syncthreads();

    // ---- epilogue: passes of 64 rows through smem staging [64][132] ----
    float* stg = (float*)sm;
    #pragma unroll 1
    for (int pass = 0; pass < BM / 64; ++pass) {
        if ((wm >> 1) == pass) {
            #pragma unroll
            for (int mf = 0; mf < 2; ++mf)
                #pragma unroll
                for (int nf = 0; nf < NF; ++nf) {
                    const int rl  = (wm & 1) * 32 + mf * 16 + g;
                    const int col = wn * (NF * 8) + nf * 8 + 2 * tig;
                    *(float2*)&stg[rl * 132 + col] =
                        make_float2(acc[mf][nf][0], acc[mf][nf][1]);
                    *(float2*)&stg[(rl + 8) * 132 + col] =
                        make_float2(acc[mf][nf][2], acc[mf][nf][3]);
                }
        }
        __syncthreads();
        {
            const int rl = tid >> 2;
            const int q  = tid & 3;
            const int rm = m0 + pass * 64 + rl;
            if (rm < cnt) {
                float* dst;
                if (FIRST) dst = g_h + (size_t)(off + rm) * DFF + n0 + q * 32;
                else       dst = Y   + (size_t)g_tok[off + rm] * DOUT + n0 + q * 32;
                const float* bsrc = bias + (size_t)e * NTOT + n0 + q * 32;
                const float* s    = stg + rl * 132 + q * 32;
                #pragma unroll
                for (int j = 0; j < 8; ++j) {
                    float4 v  = *(const float4*)(s + 4 * j);
                    float4 bb = *(const float4*)(bsrc + 4 * j);
                    v.x += bb.x; v.y += bb.y; v.z += bb.z; v.w += bb.w;
                    if (FIRST) {
                        v.x = __uint_as_float(f2tf(fmaxf(v.x, 0.f)));
                        v.y = __uint_as_float(f2tf(fmaxf(v.y, 0.f)));
                        v.z = __uint_as_float(f2tf(fmaxf(v.z, 0.f)));
                        v.w = __uint_as_float(f2tf(fmaxf(v.w, 0.f)));
                    }
                    *(float4*)(dst + 4 * j) = v;
                }
            }
        }
        __syncthreads();
    }
}

// ===========================================================================
// kernel_launch: route -> gather_x -> GEMM1(128x128) -> GEMM2(64x128).
// No allocs, no syncs, no cudaFuncSetAttribute (smem <= 48KB).
// ===========================================================================
extern "C" void kernel_launch(void* const* d_in, const int* in_sizes, int n_in,
                              void* d_out, int out_size)
{
    const float* x      = (const float*)d_in[0];
    const int*   groups = (const int*)  d_in[1];
    const float* W1     = (const float*)d_in[2];
    const float* b1     = (const float*)d_in[3];
    const float* W2     = (const float*)d_in[4];
    const float* b2     = (const float*)d_in[5];
    float*       out    = (float*)d_out;

    constexpr int SMEM1 = 3 * (128 * 64 + 8192);   // 49152 (48KB cap exactly)
    constexpr int SMEM2 = 3 * (64 * 64 + 8192);    // 36864

    route_kernel<<<1, 512>>>(groups);
    gather_x<<<BTOK, DIN / 4>>>(x);
    moe_mma_gemm<DIN, DFF, true,  128><<<dim3(DFF / 128, MAXT),   256, SMEM1>>>(W1, b1, nullptr);
    moe_mma_gemm<DFF, DOUT, false, 64><<<dim3(DOUT / 128, MAXT64), 256, SMEM2>>>(W2, b2, out);
}